// round 9
// baseline (speedup 1.0000x reference)
#include <cuda_runtime.h>

// weight: [2304, 1280] fp32 (G=48); grid_thw = [[2,64,64]]*8
// output: 65536 x 1280 fp32 (335.5 MB) — DRAM-write-bound.
//
// Output row = k*4096 + hb*128 + wb*4 + (hm*2+wm), k = 2e+t in [0,16).
// Champion structure (R2, 51.7us): per-(hb,wb) patch, 640 threads, each
// thread computes 2 sub-rows once, 16 k-replica float4 stores via __stcs
// (evict-first keeps the 11.8 MB weight table L2-resident across graph
// replays — the one proven steady-state win; all other levers lost).
//
// R9 single change: persistent grid-stride loop, grid = 296 = 2 CTAs/SM
// exactly. R2 had 1024 CTAs -> 3.46 waves with a 46%-occupancy tail wave;
// grid-stride removes wave quantization entirely. Same stores, same data,
// bitwise-identical output.

#define G_    48
#define D_    1280
#define V4_   320          // float4 per row
#define REPS  16
#define NPATCH 1024
#define ROWSTRIDE4 (4096 * V4_)   // float4 stride between k-replicas

__global__ __launch_bounds__(640)
void pe_patch_persist_kernel(const float* __restrict__ W, float* __restrict__ out)
{
    const int tid = threadIdx.x;         // 0..639
    const int s   = (tid >= V4_) ? 1 : 0;
    const int c   = tid - s * V4_;       // float4 column 0..319

    float4* __restrict__ o = (float4*)out;

    for (int pid = blockIdx.x; pid < NPATCH; pid += gridDim.x) {
        const int hb = pid >> 5;         // 0..31
        const int wb = pid & 31;         // 0..31

        // This thread computes sub-rows m = s and m = s+2  (m = hm*2 + wm)
        float4 v[2];
        #pragma unroll
        for (int j = 0; j < 2; ++j) {
            const int m  = s + 2 * j;
            const int hm = m >> 1;
            const int wm = m & 1;
            const int h  = 2 * hb + hm;
            const int w  = 2 * wb + wm;

            // linspace(0,47,64): v = i*47/63; int numerator -> exact floor
            const float vh = (float)(h * (G_ - 1)) * (1.0f / 63.0f);
            const float vw = (float)(w * (G_ - 1)) * (1.0f / 63.0f);
            const int hf = (int)vh;
            const int wf = (int)vw;
            const int hc = min(hf + 1, G_ - 1);
            const int wc = min(wf + 1, G_ - 1);
            const float dh = vh - (float)hf;
            const float dw = vw - (float)wf;

            const float c00 = (1.0f - dh) * (1.0f - dw);
            const float c01 = (1.0f - dh) * dw;
            const float c10 = dh * (1.0f - dw);
            const float c11 = dh * dw;

            const float4 a = *(const float4*)(W + (size_t)(hf * G_ + wf) * D_ + 4 * c);
            const float4 b = *(const float4*)(W + (size_t)(hf * G_ + wc) * D_ + 4 * c);
            const float4 p = *(const float4*)(W + (size_t)(hc * G_ + wf) * D_ + 4 * c);
            const float4 q = *(const float4*)(W + (size_t)(hc * G_ + wc) * D_ + 4 * c);

            v[j].x = c00 * a.x + c01 * b.x + c10 * p.x + c11 * q.x;
            v[j].y = c00 * a.y + c01 * b.y + c10 * p.y + c11 * q.y;
            v[j].z = c00 * a.z + c01 * b.z + c10 * p.z + c11 * q.z;
            v[j].w = c00 * a.w + c01 * b.w + c10 * p.w + c11 * q.w;
        }

        const int rb = hb * 128 + wb * 4;   // base output row of this patch
        const size_t base0 = (size_t)(rb + s)     * V4_ + c;
        const size_t base1 = (size_t)(rb + s + 2) * V4_ + c;

        #pragma unroll
        for (int k = 0; k < REPS; ++k) {
            const size_t off = (size_t)k * ROWSTRIDE4;
            __stcs(o + base0 + off, v[0]);   // streaming: output never re-read
            __stcs(o + base1 + off, v[1]);
        }
    }
}

extern "C" void kernel_launch(void* const* d_in, const int* in_sizes, int n_in,
                              void* d_out, int out_size)
{
    const float* weight = (const float*)d_in[0];
    (void)in_sizes; (void)n_in; (void)out_size;
    // 296 CTAs = 2 per SM on 148 SMs: zero wave-quantization tail.
    pe_patch_persist_kernel<<<296, 640>>>(weight, (float*)d_out);
}

// round 10
// speedup vs baseline: 1.1179x; 1.1179x over previous
#include <cuda_runtime.h>

// weight: [2304, 1280] fp32 (G=48); grid_thw = [[2,64,64]]*8
// output: 65536 x 1280 fp32 (335.5 MB) — DRAM-write-bound.
//
// Output row = k*4096 + hb*128 + wb*4 + (hm*2+wm), k = 2e+t in [0,16).
// Evidence so far: DRAM busy rises monotonically with concurrent CTA count
// (296 CTAs: 62.9%, 1024: 66.3%, 4096: 67.2%), and __stcs on output stores
// is worth ~4us in the graph-replay steady state (keeps the 11.8 MB weight
// table L2-resident). R10 composes the two proven wins: R1's 4096-CTA
// high-concurrency grid + .cs streaming stores. One CTA per distinct (h,w)
// row; 320 threads = one float4 column each; 16 k-replica stores.

#define G_   48
#define D_   1280
#define HW_  4096        // 64*64 distinct (h,w)
#define V4_  320         // D_/4 float4 per row
#define REPS 16
#define ROWSTRIDE4 (4096 * V4_)

__global__ __launch_bounds__(V4_)
void pe_interp_cs_kernel(const float* __restrict__ W, float* __restrict__ out)
{
    const int hw = blockIdx.x;        // 0..4095
    const int h  = hw >> 6;           // 0..63
    const int w  = hw & 63;

    // linspace(0,47,64): v = i*47/63; integer numerator -> exact floor
    const float vh = (float)(h * (G_ - 1)) * (1.0f / 63.0f);
    const float vw = (float)(w * (G_ - 1)) * (1.0f / 63.0f);
    const int hf = (int)vh;
    const int wf = (int)vw;
    const int hc = min(hf + 1, G_ - 1);
    const int wc = min(wf + 1, G_ - 1);
    const float dh = vh - (float)hf;
    const float dw = vw - (float)wf;

    const float c00 = (1.0f - dh) * (1.0f - dw);
    const float c01 = (1.0f - dh) * dw;
    const float c10 = dh * (1.0f - dw);
    const float c11 = dh * dw;

    const int c = threadIdx.x;        // 0..319: float4 column

    const float4* __restrict__ r00 = (const float4*)(W + (size_t)(hf * G_ + wf) * D_);
    const float4* __restrict__ r01 = (const float4*)(W + (size_t)(hf * G_ + wc) * D_);
    const float4* __restrict__ r10 = (const float4*)(W + (size_t)(hc * G_ + wf) * D_);
    const float4* __restrict__ r11 = (const float4*)(W + (size_t)(hc * G_ + wc) * D_);

    const float4 a = r00[c];
    const float4 b = r01[c];
    const float4 p = r10[c];
    const float4 q = r11[c];

    float4 v;
    v.x = c00 * a.x + c01 * b.x + c10 * p.x + c11 * q.x;
    v.y = c00 * a.y + c01 * b.y + c10 * p.y + c11 * q.y;
    v.z = c00 * a.z + c01 * b.z + c10 * p.z + c11 * q.z;
    v.w = c00 * a.w + c01 * b.w + c10 * p.w + c11 * q.w;

    // destination row within one k-block of 4096 rows
    const int hb = h >> 1, hm = h & 1;
    const int wb = w >> 1, wm = w & 1;
    const int rloc = hb * 128 + wb * 4 + hm * 2 + wm;

    float4* __restrict__ o = (float4*)out;
    const size_t base = (size_t)rloc * V4_ + c;

    #pragma unroll
    for (int k = 0; k < REPS; ++k)
        __stcs(o + base + (size_t)k * ROWSTRIDE4, v);   // streaming stores
}

extern "C" void kernel_launch(void* const* d_in, const int* in_sizes, int n_in,
                              void* d_out, int out_size)
{
    const float* weight = (const float*)d_in[0];
    (void)in_sizes; (void)n_in; (void)out_size;
    pe_interp_cs_kernel<<<HW_, V4_>>>(weight, (float*)d_out);
}

// round 11
// speedup vs baseline: 1.1186x; 1.0006x over previous
#include <cuda_runtime.h>

// weight: [2304, 1280] fp32 (G=48); grid_thw = [[2,64,64]]*8
// output: 65536 x 1280 fp32 (335.5 MB) — DRAM-write-bound.
//
// Output row = k*4096 + hb*128 + wb*4 + (hm*2+wm), k = 2e+t in [0,16).
// Evidence: DRAM busy rises monotonically with RESIDENT warp/CTA count;
// .cs streaming stores keep the 11.8 MB weight table L2-resident across
// graph replays (~4us steady-state win). R10 (4096 CTAs x 320thr, .cs)
// = 51.3us best.
//
// R11: flatten to one thread per (distinct row, float4 column):
// 4096*320 threads in 256-thread blocks -> 5120 CTAs, 8 CTAs/SM,
// 64/64 warps (vs 60/64), 1184 resident CTAs (vs 888). 32 | 320, so a
// warp never straddles a row: coalescing unchanged. Same math, same
// stores, bitwise-identical output.

#define G_   48
#define D_   1280
#define V4_  320         // float4 per row
#define REPS 16
#define ROWSTRIDE4 (4096 * V4_)
#define NTHREADS (4096 * V4_)

__global__ __launch_bounds__(256)
void pe_interp_flat_kernel(const float* __restrict__ W, float* __restrict__ out)
{
    const int gid = blockIdx.x * 256 + threadIdx.x;   // 0 .. 4096*320-1
    const int hw  = gid / V4_;        // distinct row 0..4095
    const int c   = gid - hw * V4_;   // float4 column 0..319

    const int h = hw >> 6;            // 0..63
    const int w = hw & 63;

    // linspace(0,47,64): v = i*47/63; integer numerator -> exact floor
    const float vh = (float)(h * (G_ - 1)) * (1.0f / 63.0f);
    const float vw = (float)(w * (G_ - 1)) * (1.0f / 63.0f);
    const int hf = (int)vh;
    const int wf = (int)vw;
    const int hc = min(hf + 1, G_ - 1);
    const int wc = min(wf + 1, G_ - 1);
    const float dh = vh - (float)hf;
    const float dw = vw - (float)wf;

    const float c00 = (1.0f - dh) * (1.0f - dw);
    const float c01 = (1.0f - dh) * dw;
    const float c10 = dh * (1.0f - dw);
    const float c11 = dh * dw;

    const float4 a = *(const float4*)(W + (size_t)(hf * G_ + wf) * D_ + 4 * c);
    const float4 b = *(const float4*)(W + (size_t)(hf * G_ + wc) * D_ + 4 * c);
    const float4 p = *(const float4*)(W + (size_t)(hc * G_ + wf) * D_ + 4 * c);
    const float4 q = *(const float4*)(W + (size_t)(hc * G_ + wc) * D_ + 4 * c);

    float4 v;
    v.x = c00 * a.x + c01 * b.x + c10 * p.x + c11 * q.x;
    v.y = c00 * a.y + c01 * b.y + c10 * p.y + c11 * q.y;
    v.z = c00 * a.z + c01 * b.z + c10 * p.z + c11 * q.z;
    v.w = c00 * a.w + c01 * b.w + c10 * p.w + c11 * q.w;

    // destination row within one k-block of 4096 rows
    const int hb = h >> 1, hm = h & 1;
    const int wb = w >> 1, wm = w & 1;
    const int rloc = hb * 128 + wb * 4 + hm * 2 + wm;

    float4* __restrict__ o = (float4*)out;
    const size_t base = (size_t)rloc * V4_ + c;

    #pragma unroll
    for (int k = 0; k < REPS; ++k)
        __stcs(o + base + (size_t)k * ROWSTRIDE4, v);   // streaming stores
}

extern "C" void kernel_launch(void* const* d_in, const int* in_sizes, int n_in,
                              void* d_out, int out_size)
{
    const float* weight = (const float*)d_in[0];
    (void)in_sizes; (void)n_in; (void)out_size;
    pe_interp_flat_kernel<<<NTHREADS / 256, 256>>>(weight, (float*)d_out);
}